// round 2
// baseline (speedup 1.0000x reference)
#include <cuda_runtime.h>
#include <cstdint>

#define BB 64
#define HH 512
#define WW 512
#define NBOX 160
#define SLABS 8
#define SLAB_ROWS 64   // HH / SLABS
#define THREADS 256    // each thread owns 2 columns

__device__ unsigned long long g_sall[BB];
__device__ unsigned long long g_spnt[BB];
__device__ int g_cnt[BB];

__global__ void zero_kernel() {
    int t = threadIdx.x;
    if (t < BB) { g_sall[t] = 0ull; g_spnt[t] = 0ull; g_cnt[t] = 0; }
}

// bits [p, q) with 0 <= p < q <= 64
__device__ __forceinline__ unsigned long long rmask64(int p, int q) {
    int n = q - p;
    return (~0ull >> (64 - n)) << p;
}

__global__ __launch_bounds__(THREADS)
void motion_mask_main(const float* __restrict__ pred, const int* __restrict__ tgt) {
    __shared__ int s_nact;
    __shared__ unsigned long long s_rm[NBOX];  // row mask within slab, per active box
    __shared__ int2 s_y[NBOX];                 // [y1, y2) column interval

    const int tid  = threadIdx.x;
    const int slab = blockIdx.x;
    const int b    = blockIdx.y;
    const int r0   = slab * SLAB_ROWS;

    if (tid == 0) s_nact = 0;
    __syncthreads();

    // ---- compact boxes intersecting this row slab; precompute row bitmasks ----
    if (tid < NBOX) {
        int4 t4 = ((const int4*)tgt)[b * NBOX + tid];   // (x, y, sx, sy)
        int x1 = min(t4.x, HH);
        int x2 = min(t4.x + t4.z, HH);
        int y1 = min(t4.y, WW);
        int y2 = min(t4.y + t4.w, WW);
        int a = max(x1 - r0, 0);
        int e = min(x2 - r0, SLAB_ROWS);
        if (e > a && y2 > y1) {
            int pos = atomicAdd(&s_nact, 1);
            s_rm[pos] = rmask64(a, e);
            s_y[pos]  = make_int2(y1, y2);
        }
    }
    __syncthreads();
    const int nact = s_nact;

    // ---- build per-column row-coverage masks (2 cols per thread) ----
    const int c0 = tid * 2;
    unsigned long long m0 = 0ull, m1 = 0ull;
    for (int j = 0; j < nact; j++) {
        int2 yy = s_y[j];
        unsigned long long rm = s_rm[j];
        if (yy.x <= c0     && c0     < yy.y) m0 |= rm;
        if (yy.x <= c0 + 1 && c0 + 1 < yy.y) m1 |= rm;
    }
    int cnt = __popcll(m0) + __popcll(m1);

    // ---- pixel loop: sigmoid + masked accumulation ----
    const float2* base =
        (const float2*)(pred + (size_t)b * HH * WW + (size_t)r0 * WW) + tid;
    float s_all = 0.f, s_pnt = 0.f;
#pragma unroll 8
    for (int rr = 0; rr < SLAB_ROWS; rr++) {
        float2 v = base[rr * (WW / 2)];
        float t0 = __expf(-v.x);
        float t1 = __expf(-v.y);
        float sg0 = __fdividef(1.f, 1.f + t0);
        float sg1 = __fdividef(1.f, 1.f + t1);
        s_all += sg0 + sg1;
        s_pnt += ((m0 >> rr) & 1ull) ? sg0 : 0.f;
        s_pnt += ((m1 >> rr) & 1ull) ? sg1 : 0.f;
    }

    // ---- block reduction ----
#pragma unroll
    for (int o = 16; o; o >>= 1) {
        s_all += __shfl_down_sync(0xFFFFFFFFu, s_all, o);
        s_pnt += __shfl_down_sync(0xFFFFFFFFu, s_pnt, o);
        cnt   += __shfl_down_sync(0xFFFFFFFFu, cnt, o);
    }
    __shared__ float w_all[THREADS / 32], w_pnt[THREADS / 32];
    __shared__ int   w_cnt[THREADS / 32];
    const int lane = tid & 31, warp = tid >> 5;
    if (lane == 0) { w_all[warp] = s_all; w_pnt[warp] = s_pnt; w_cnt[warp] = cnt; }
    __syncthreads();
    if (tid == 0) {
        float ta = 0.f, tp = 0.f; int tc = 0;
#pragma unroll
        for (int i = 0; i < THREADS / 32; i++) { ta += w_all[i]; tp += w_pnt[i]; tc += w_cnt[i]; }
        // deterministic fixed-point (2^24) accumulation across CTAs
        atomicAdd(&g_sall[b], (unsigned long long)__double2ll_rn((double)ta * 16777216.0));
        atomicAdd(&g_spnt[b], (unsigned long long)__double2ll_rn((double)tp * 16777216.0));
        atomicAdd(&g_cnt[b], tc);
    }
}

__global__ void final_kernel(float* __restrict__ out) {
    __shared__ double s_loss[BB];
    int t = threadIdx.x;
    double S  = (double)g_sall[t] * (1.0 / 16777216.0);   // pred_sum
    double Sp = (double)g_spnt[t] * (1.0 / 16777216.0);   // sum(pred) over painted
    double T  = 255.0 * (double)g_cnt[t];                 // target_sum
    double I  = 255.0 * Sp;                               // intersection
    s_loss[t] = (I + 1.0) / (S + T - I + 1.0);
    __syncthreads();
    if (t == 0) {
        double acc = 0.0;
        for (int i = 0; i < BB; i++) acc += s_loss[i];
        out[0] = (float)(1.0 - acc / (double)BB);
    }
}

extern "C" void kernel_launch(void* const* d_in, const int* in_sizes, int n_in,
                              void* d_out, int out_size) {
    const float* pred = (const float*)d_in[0];   // pred_m  f32 (64,1,512,512)
    const int*   tgt  = (const int*)d_in[1];     // multi_targets i32 (64,5,32,4)
    float* out = (float*)d_out;

    zero_kernel<<<1, BB>>>();
    dim3 grid(SLABS, BB);
    motion_mask_main<<<grid, THREADS>>>(pred, tgt);
    final_kernel<<<1, BB>>>(out);
}